// round 15
// baseline (speedup 1.0000x reference)
#include <cuda_runtime.h>

// Patch2Im gather, cp.async-staged:
//  Phase 1: block cooperatively streams its input working set
//           (4 channels x nrow x 7 j-planes x 85 floats) into smem via
//           4B cp.async — no result registers => massive MLP.
//  Phase 2: residue-major threads compute outputs from smem.
// out[bc,h,w] = mean over valid (i,j) of xp[bc,i,j,ph,pw],
//   h+3 = i + 3*ph, w+3 = j + 3*pw.

#define PS 7225               // 85*85
#define CST (7 * PS)
#define CHS (49 * PS)
#define OH 253
#define OW 253
#define OCH (OH * OW)
#define NCHB 4                // channels per block (consecutive)

__device__ __forceinline__ unsigned smem_addr_u32(const void* p) {
    return (unsigned)__cvta_generic_to_shared(p);
}

template <int NR>
__device__ __forceinline__ void run_case(
    const float* __restrict__ base,   // xp + first channel of this block
    float* __restrict__ outbase,      // out + first channel, row h
    int qh, int rh, float* sm, int tid)
{
    // ---------------- Phase 1: cp.async load ----------------
    // smem layout: sm[((ch*NR + a)*7 + j)*85 + pw]
    constexpr int TOTAL = NCHB * NR * 7 * 85;
    constexpr int ITER  = (TOTAL + 255) / 256;
#pragma unroll
    for (int it = 0; it < ITER; ++it) {
        int idx = tid + it * 256;
        if (idx < TOTAL) {
            int seg = idx / 85;
            int off = idx - seg * 85;
            int ch  = seg / (NR * 7);
            int rem = seg - ch * (NR * 7);
            int a   = rem / 7;
            int j   = rem - a * 7;
            int ph  = qh - a;
            ph = ph < 0 ? 0 : (ph > 84 ? 84 : ph);   // clamp; weight 0 kills it
            const float* g = base + (size_t)ch * CHS + (rh + 3 * a) * CST
                           + j * PS + ph * 85 + off;
            unsigned d = smem_addr_u32(sm + idx);
            asm volatile("cp.async.ca.shared.global [%0], [%1], 4;\n"
                         :: "r"(d), "l"(g));
        }
    }
    asm volatile("cp.async.commit_group;\n");
    asm volatile("cp.async.wait_group 0;\n");
    __syncthreads();

    // ---------------- Phase 2: compute from smem ----------------
    int s = tid;
    if (s >= 253) return;
    int r, q;
    if (s < 85)       { r = 0; q = s; }
    else if (s < 169) { r = 1; q = s - 85; }
    else              { r = 2; q = s - 169; }

#define SEG(ch, a, j) ((((ch) * NR + (a)) * 7 + (j)) * 85)

    float res[NCHB];

    if (NR == 3) {                       // rows i = 0,3,6
        float wr0 = (qh <= 84) ? 1.f : 0.f;
        float wr2 = (qh >= 2)  ? 1.f : 0.f;
        float inr = (wr0 + wr2 == 2.f) ? (1.f / 3.f) : 0.5f;

        if (r == 0) {                    // cols j = 0,3,6
            float wc0 = (q <= 83) ? 1.f : 0.f;
            float wc2 = (q >= 1)  ? 1.f : 0.f;
            int pw0 = (q <= 83) ? q + 1 : 84;
            int pw1 = q;
            int pw2 = (q >= 1)  ? q - 1 : 0;
            float scale = inr * ((wc0 + wc2 == 2.f) ? (1.f / 3.f) : 0.5f);
#pragma unroll
            for (int ch = 0; ch < NCHB; ++ch) {
                float s0 = wr0 * sm[SEG(ch,0,0) + pw0] + sm[SEG(ch,1,0) + pw0] + wr2 * sm[SEG(ch,2,0) + pw0];
                float s1 = wr0 * sm[SEG(ch,0,3) + pw1] + sm[SEG(ch,1,3) + pw1] + wr2 * sm[SEG(ch,2,3) + pw1];
                float s2 = wr0 * sm[SEG(ch,0,6) + pw2] + sm[SEG(ch,1,6) + pw2] + wr2 * sm[SEG(ch,2,6) + pw2];
                res[ch] = (wc0 * s0 + s1 + wc2 * s2) * scale;
            }
        } else {                         // cols j = r, r+3 (always valid)
            int pwa = q + 1, pwb = q;
            float scale = inr * 0.5f;
#pragma unroll
            for (int ch = 0; ch < NCHB; ++ch) {
                float s0 = wr0 * sm[SEG(ch,0,r)   + pwa] + sm[SEG(ch,1,r)   + pwa] + wr2 * sm[SEG(ch,2,r)   + pwa];
                float s1 = wr0 * sm[SEG(ch,0,r+3) + pwb] + sm[SEG(ch,1,r+3) + pwb] + wr2 * sm[SEG(ch,2,r+3) + pwb];
                res[ch] = (s0 + s1) * scale;
            }
        }
    } else {                             // NR == 2: rows i = rh, rh+3 (valid)
        if (r == 0) {
            float wc0 = (q <= 83) ? 1.f : 0.f;
            float wc2 = (q >= 1)  ? 1.f : 0.f;
            int pw0 = (q <= 83) ? q + 1 : 84;
            int pw1 = q;
            int pw2 = (q >= 1)  ? q - 1 : 0;
            float scale = 0.5f * ((wc0 + wc2 == 2.f) ? (1.f / 3.f) : 0.5f);
#pragma unroll
            for (int ch = 0; ch < NCHB; ++ch) {
                float s0 = sm[SEG(ch,0,0) + pw0] + sm[SEG(ch,1,0) + pw0];
                float s1 = sm[SEG(ch,0,3) + pw1] + sm[SEG(ch,1,3) + pw1];
                float s2 = sm[SEG(ch,0,6) + pw2] + sm[SEG(ch,1,6) + pw2];
                res[ch] = (wc0 * s0 + s1 + wc2 * s2) * scale;
            }
        } else {                         // pure interior 2x2
            int pwa = q + 1, pwb = q;
#pragma unroll
            for (int ch = 0; ch < NCHB; ++ch) {
                res[ch] = (sm[SEG(ch,0,r)   + pwa] + sm[SEG(ch,1,r)   + pwa]
                         + sm[SEG(ch,0,r+3) + pwb] + sm[SEG(ch,1,r+3) + pwb]) * 0.25f;
            }
        }
    }
#undef SEG

    float* op = outbase + (3 * q + r);
#pragma unroll
    for (int ch = 0; ch < NCHB; ++ch)
        op[(size_t)ch * OCH] = res[ch];
}

__global__ void __launch_bounds__(256)
patch2im_kernel(const float* __restrict__ xp, float* __restrict__ out)
{
    __shared__ float sm[NCHB * 3 * 7 * 85];   // 28560 B max (NR=3)

    int tid = threadIdx.x;
    int h   = blockIdx.x;                 // 0..252
    int bc0 = blockIdx.y;                 // 0..63 ; channels 4*bc0..4*bc0+3

    int hp = h + 3;
    int qh = hp / 3;                      // 1..85
    int rh = hp % 3;

    const float* base = xp + (size_t)(NCHB * bc0) * CHS;
    float* outbase = out + (size_t)(NCHB * bc0) * OCH + (size_t)h * OW;

    if (rh == 0) run_case<3>(base, outbase, qh, rh, sm, tid);
    else         run_case<2>(base, outbase, qh, rh, sm, tid);
}

extern "C" void kernel_launch(void* const* d_in, const int* in_sizes, int n_in,
                              void* d_out, int out_size)
{
    const float* xp = (const float*)d_in[0];
    float* outp = (float*)d_out;
    dim3 grid(OH, 64);                    // (h, bc/4)
    patch2im_kernel<<<grid, 256>>>(xp, outp);
}